// round 2
// baseline (speedup 1.0000x reference)
#include <cuda_runtime.h>
#include <cstdint>

typedef unsigned long long ull;

// ---------------- constants ----------------
#define NDICT   50000
#define DIN     256
#define DH      256
#define NGATE   1024
#define BB      256
#define SS      512
#define NBLK    128
// scan smem: hs_dup[256][16 floats(8 b dup'd x2)]... actually [256][64] + Us[256][132]
#define HS_PITCH 64
#define US_PITCH 132
#define HS_FLOATS (256 * HS_PITCH)
#define SCAN_SMEM ((HS_FLOATS + 256 * US_PITCH) * 4)

// ---------------- device scratch ----------------
__device__ float g_EW[(size_t)NDICT * NGATE];   // Emb@W^T + bias, cols permuted j*4+type
__device__ float g_h[2 * 2 * DH * BB];          // [buf][dir][j][b]
__device__ int   g_wordsT[SS * BB];             // words transposed [s][b]
__device__ unsigned g_flags[NBLK * 8];          // barrier flags, 32B stride

// ---------------- f32x2 helpers ----------------
__device__ __forceinline__ ull pk(float x, float y) {
    ull r; asm("mov.b64 %0, {%1, %2};" : "=l"(r) : "f"(x), "f"(y)); return r;
}
__device__ __forceinline__ void upk(ull v, float& x, float& y) {
    asm("mov.b64 {%0, %1}, %2;" : "=f"(x), "=f"(y) : "l"(v));
}
__device__ __forceinline__ void fma2(ull& d, ull a, ull b) {
    asm("fma.rn.f32x2 %0, %1, %2, %0;" : "+l"(d) : "l"(a), "l"(b));
}
// fast, overflow-safe activations (MUFU EX2 + RCP paths)
__device__ __forceinline__ float fsig(float x) {
    float e = __expf(-x);                 // x<<0 -> e=inf -> 1/(1+inf)=0 (rcp(inf)=0) OK
    return __fdividef(1.0f, 1.0f + e);
}
__device__ __forceinline__ float ftanh(float x) {
    float ax = fabsf(x);
    float e  = __expf(-2.0f * ax);        // e in (0,1], no overflow
    float r  = __fdividef(1.0f - e, 1.0f + e);
    return copysignf(r, x);
}

// ---------------- kernel 0: reset flags + transpose words ----------------
__global__ void reset_kernel(const int* __restrict__ words) {
    int idx = blockIdx.x * blockDim.x + threadIdx.x;
    if (idx < NBLK * 8) g_flags[idx] = 0u;
    for (int i = idx; i < SS * BB; i += gridDim.x * blockDim.x) {
        int s = i >> 8, b = i & 255;
        g_wordsT[i] = words[b * SS + s];
    }
}

// ---------------- kernel 1: EW = Emb @ W^T (+bias), columns permuted ----------------
__global__ __launch_bounds__(256) void ew_gemm(const float* __restrict__ Emb,
                                               const float* __restrict__ W,
                                               const float* __restrict__ bias) {
    __shared__ __align__(16) float As[16][68];
    __shared__ __align__(16) float Bs[16][68];
    int tid = threadIdx.x;
    int mbase = blockIdx.x * 64;
    int nbase = blockIdx.y * 64;
    int tx = tid & 15, ty = tid >> 4;
    int lr = tid >> 2, lk = (tid & 3) * 4;

    ull acc[4][2];
#pragma unroll
    for (int r = 0; r < 4; r++) { acc[r][0] = 0ull; acc[r][1] = 0ull; }

    int colp_l = nbase + lr;
    int grow_l = (colp_l & 3) * 256 + (colp_l >> 2);
    int va = mbase + lr;

    for (int kb = 0; kb < DIN; kb += 16) {
        float4 av = make_float4(0.f, 0.f, 0.f, 0.f);
        if (va < NDICT) av = *(const float4*)&Emb[(size_t)va * DIN + kb + lk];
        As[lk + 0][lr] = av.x; As[lk + 1][lr] = av.y;
        As[lk + 2][lr] = av.z; As[lk + 3][lr] = av.w;
        float4 bv = *(const float4*)&W[(size_t)grow_l * DIN + kb + lk];
        Bs[lk + 0][lr] = bv.x; Bs[lk + 1][lr] = bv.y;
        Bs[lk + 2][lr] = bv.z; Bs[lk + 3][lr] = bv.w;
        __syncthreads();
#pragma unroll
        for (int kk = 0; kk < 16; kk++) {
            float4 a = *(float4*)&As[kk][ty * 4];
            float4 b4 = *(float4*)&Bs[kk][tx * 4];
            ull b01 = pk(b4.x, b4.y), b23 = pk(b4.z, b4.w);
            ull h;
            h = pk(a.x, a.x); fma2(acc[0][0], h, b01); fma2(acc[0][1], h, b23);
            h = pk(a.y, a.y); fma2(acc[1][0], h, b01); fma2(acc[1][1], h, b23);
            h = pk(a.z, a.z); fma2(acc[2][0], h, b01); fma2(acc[2][1], h, b23);
            h = pk(a.w, a.w); fma2(acc[3][0], h, b01); fma2(acc[3][1], h, b23);
        }
        __syncthreads();
    }

    int colp0 = nbase + tx * 4;
    int jj = colp0 >> 2;
    float bi = bias[jj], bf = bias[256 + jj], bo = bias[512 + jj], bc = bias[768 + jj];
#pragma unroll
    for (int r = 0; r < 4; r++) {
        int v = mbase + ty * 4 + r;
        if (v < NDICT) {
            float o0, o1, o2, o3;
            upk(acc[r][0], o0, o1); upk(acc[r][1], o2, o3);
            float4 out = make_float4(o0 + bi, o1 + bf, o2 + bo, o3 + bc);
            *(float4*)&g_EW[(size_t)v * NGATE + colp0] = out;
        }
    }
}

// ---------------- kernel 2: persistent bidirectional LSTM scan ----------------
// grid = 128 CTAs: dir(2) x batch-tile(8, 32 rows) x gate-slice(8, 32 j / 128 cols)
// 128 threads, thread tile = 8 batch rows x 4 gate cols (one j, 4 types)
__global__ __launch_bounds__(128, 1) void scan_kernel(const float* __restrict__ U) {
    extern __shared__ float sm[];
    float* hs = sm;                 // [256 k][64] : 32 b values duplicated as pairs
    float* Us = sm + HS_FLOATS;     // [256 k][132]: 128 permuted gate cols + pad

    int tid = threadIdx.x;
    int bx = blockIdx.x;
    int dir = bx >> 6;
    int bt  = (bx >> 3) & 7;
    int js  = bx & 7;
    int tx = tid & 31, ty = tid >> 5;       // tx: j within slice; ty: batch octet
    int j = js * 32 + tx;                   // this thread's hidden unit
    int bbase = bt * 32 + ty * 8;           // first of this thread's 8 batch rows

    // preload U slice: Us[k][col] = U[type*256 + js*32 + jl][k], col = jl*4+type
    for (int i = tid; i < 128 * 256; i += 128) {
        int col = i >> 8, k = i & 255;
        int type = col & 3, jl = col >> 2;
        Us[k * US_PITCH + col] = U[(size_t)(type * 256 + js * 32 + jl) * DH + k];
    }

    float c[8];
#pragma unroll
    for (int r = 0; r < 8; r++) c[r] = 0.f;
    __syncthreads();

    for (int t = 0; t < SS; t++) {
        int cur = t & 1, nxt = cur ^ 1;
        int s = dir ? (SS - 1 - t) : t;

        // prefetch EW rows (gates-input + bias) for this thread's 8 batch rows
        float4 e[8];
#pragma unroll
        for (int r = 0; r < 8; r++) {
            int w = g_wordsT[s * BB + bbase + r];
            e[r] = __ldg((const float4*)&g_EW[(size_t)w * NGATE + j * 4]);
        }

        // stage h(t) [256 k][32 b] -> smem duplicated pairs [256][64]
        const float* hsrc = g_h + (size_t)(cur * 2 + dir) * DH * BB + bt * 32;
        for (int i = tid; i < 2048; i += 128) {
            int k = i >> 3, b4 = (i & 7) << 2;
            float4 v = __ldcg((const float4*)&hsrc[k * BB + b4]);
            float* d = &hs[k * HS_PITCH + (b4 << 1)];
            ((float4*)d)[0] = make_float4(v.x, v.x, v.y, v.y);
            ((float4*)d)[1] = make_float4(v.z, v.z, v.w, v.w);
        }
        __syncthreads();

        // gates tile: [8 batch rows x 4 gate cols] = h @ U^T (slice)
        ull a[8][2];
#pragma unroll
        for (int r = 0; r < 8; r++) { a[r][0] = 0ull; a[r][1] = 0ull; }

        const float* hp = hs + ty * 16;
        const float* up = Us + tx * 4;
#pragma unroll 4
        for (int k = 0; k < 256; k++) {
            ulonglong2 hA = *(const ulonglong2*)(hp);        // (b0,b0),(b1,b1)
            ulonglong2 hB = *(const ulonglong2*)(hp + 4);    // (b2,b2),(b3,b3)
            ulonglong2 hC = *(const ulonglong2*)(hp + 8);    // (b4,b4),(b5,b5)
            ulonglong2 hD = *(const ulonglong2*)(hp + 12);   // (b6,b6),(b7,b7)
            ulonglong2 uu = *(const ulonglong2*)(up);        // (u0,u1),(u2,u3)
            fma2(a[0][0], hA.x, uu.x); fma2(a[0][1], hA.x, uu.y);
            fma2(a[1][0], hA.y, uu.x); fma2(a[1][1], hA.y, uu.y);
            fma2(a[2][0], hB.x, uu.x); fma2(a[2][1], hB.x, uu.y);
            fma2(a[3][0], hB.y, uu.x); fma2(a[3][1], hB.y, uu.y);
            fma2(a[4][0], hC.x, uu.x); fma2(a[4][1], hC.x, uu.y);
            fma2(a[5][0], hC.y, uu.x); fma2(a[5][1], hC.y, uu.y);
            fma2(a[6][0], hD.x, uu.x); fma2(a[6][1], hD.x, uu.y);
            fma2(a[7][0], hD.y, uu.x); fma2(a[7][1], hD.y, uu.y);
            hp += HS_PITCH; up += US_PITCH;
        }

        // epilogue: activations + c update (c in registers), h out
        float hout[8];
#pragma unroll
        for (int r = 0; r < 8; r++) {
            float gi, gf, go, gc;
            upk(a[r][0], gi, gf); upk(a[r][1], go, gc);
            gi = fsig(gi + e[r].x); gf = fsig(gf + e[r].y);
            go = fsig(go + e[r].z); gc = ftanh(gc + e[r].w);
            c[r] = gf * c[r] + gi * gc;
            hout[r] = go * ftanh(c[r]);
        }
        float* hdst = g_h + (size_t)((nxt * 2 + dir) * DH + j) * BB + bbase;
        __stcg((float4*)hdst, make_float4(hout[0], hout[1], hout[2], hout[3]));
        __stcg((float4*)(hdst + 4), make_float4(hout[4], hout[5], hout[6], hout[7]));

        __syncthreads();   // all hs reads done, all h stores issued
        if (t < SS - 1) {
            if (tid == 0) {
                asm volatile("st.release.gpu.u32 [%0], %1;"
                             :: "l"(&g_flags[bx * 8]), "r"(t + 1) : "memory");
            }
            // 128 threads each poll one CTA's flag (distinct 32B-strided lines)
            {
                unsigned* fp = &g_flags[tid * 8];
                unsigned v;
                do {
                    asm volatile("ld.acquire.gpu.u32 %0, [%1];"
                                 : "=r"(v) : "l"(fp) : "memory");
                } while ((int)v < t + 1);
            }
            __syncthreads();
        }
    }
}

// ---------------- kernel 3: output layer (one block per batch row) ----------------
__global__ void out_kernel(const float* __restrict__ outW,
                           const float* __restrict__ outb,
                           float* __restrict__ pred) {
    int b = blockIdx.x;
    int tid = threadIdx.x;  // 128 threads
    const float* hl = g_h;                       // buf0 dir0 [j][b]
    const float* hr = g_h + (size_t)DH * BB;     // buf0 dir1
    float a0 = 0.f, a1 = 0.f;
    for (int idx = tid; idx < 512; idx += 128) {
        float v = (idx < 256) ? hl[idx * BB + b] : hr[(idx - 256) * BB + b];
        a0 += v * outW[idx];
        a1 += v * outW[512 + idx];
    }
#pragma unroll
    for (int o = 16; o > 0; o >>= 1) {
        a0 += __shfl_down_sync(0xFFFFFFFFu, a0, o);
        a1 += __shfl_down_sync(0xFFFFFFFFu, a1, o);
    }
    __shared__ float s0[4], s1[4];
    if ((tid & 31) == 0) { s0[tid >> 5] = a0; s1[tid >> 5] = a1; }
    __syncthreads();
    if (tid == 0) {
        pred[b * 2 + 0] = s0[0] + s0[1] + s0[2] + s0[3] + outb[0];
        pred[b * 2 + 1] = s1[0] + s1[1] + s1[2] + s1[3] + outb[1];
    }
}

// ---------------- launch ----------------
extern "C" void kernel_launch(void* const* d_in, const int* in_sizes, int n_in,
                              void* d_out, int out_size) {
    const int*   words = (const int*)d_in[0];
    const float* Emb   = (const float*)d_in[1];
    const float* W     = (const float*)d_in[2];
    const float* U     = (const float*)d_in[3];
    const float* bias  = (const float*)d_in[4];
    const float* outW  = (const float*)d_in[5];
    const float* outb  = (const float*)d_in[6];
    float* pred = (float*)d_out;

    cudaFuncSetAttribute(scan_kernel, cudaFuncAttributeMaxDynamicSharedMemorySize, SCAN_SMEM);

    reset_kernel<<<256, 256>>>(words);
    ew_gemm<<<dim3((NDICT + 63) / 64, NGATE / 64), 256>>>(Emb, W, bias);
    scan_kernel<<<NBLK, 128, SCAN_SMEM>>>(U);
    out_kernel<<<256, 128>>>(outW, outb, pred);
}

// round 3
// speedup vs baseline: 1.3278x; 1.3278x over previous
#include <cuda_runtime.h>
#include <cstdint>

typedef unsigned long long ull;

// ---------------- constants ----------------
#define NDICT   50000
#define DIN     256
#define DH      256
#define NGATE   1024
#define BB      256
#define SS      512
#define NBLK    128
// scan smem: hs[256][32] (no dup) + Us[256][128]
#define HS_PITCH 32
#define US_PITCH 128
#define HS_FLOATS (256 * HS_PITCH)
#define SCAN_SMEM ((HS_FLOATS + 256 * US_PITCH) * 4)

// ---------------- device scratch ----------------
__device__ float g_EW[(size_t)NDICT * NGATE];   // Emb@W^T + bias, cols permuted j*4+type
__device__ float g_h[2 * 2 * DH * BB];          // [buf][dir][j][b]
__device__ int   g_wordsT[SS * BB];             // words transposed [s][b]
__device__ unsigned g_flags[16 * 64];           // [group(dir,bt)][js*8], 32B stride

// ---------------- f32x2 helpers ----------------
__device__ __forceinline__ ull pk(float x, float y) {
    ull r; asm("mov.b64 %0, {%1, %2};" : "=l"(r) : "f"(x), "f"(y)); return r;
}
__device__ __forceinline__ void upk(ull v, float& x, float& y) {
    asm("mov.b64 {%0, %1}, %2;" : "=f"(x), "=f"(y) : "l"(v));
}
__device__ __forceinline__ void fma2(ull& d, ull a, ull b) {
    asm("fma.rn.f32x2 %0, %1, %2, %0;" : "+l"(d) : "l"(a), "l"(b));
}
__device__ __forceinline__ float fsig(float x) {
    float e = __expf(-x);
    return __fdividef(1.0f, 1.0f + e);
}
__device__ __forceinline__ float ftanh(float x) {
    float ax = fabsf(x);
    float e  = __expf(-2.0f * ax);
    float r  = __fdividef(1.0f - e, 1.0f + e);
    return copysignf(r, x);
}

// ---------------- kernel 0: reset flags + transpose words ----------------
__global__ void reset_kernel(const int* __restrict__ words) {
    int idx = blockIdx.x * blockDim.x + threadIdx.x;
    if (idx < 16 * 64) g_flags[idx] = 0u;
    for (int i = idx; i < SS * BB; i += gridDim.x * blockDim.x) {
        int s = i >> 8, b = i & 255;
        g_wordsT[i] = words[b * SS + s];
    }
}

// ---------------- kernel 1: EW = Emb @ W^T (+bias), columns permuted ----------------
// 128 threads, tile 64m x 64n, thread tile 8m x 4n, batch(m)-paired f32x2
__global__ __launch_bounds__(128) void ew_gemm(const float* __restrict__ Emb,
                                               const float* __restrict__ W,
                                               const float* __restrict__ bias) {
    __shared__ __align__(16) float As[16][68];  // [k][m]
    __shared__ __align__(16) float Bs[16][68];  // [k][n(permuted)]
    int tid = threadIdx.x;
    int mbase = blockIdx.x * 64;
    int nbase = blockIdx.y * 64;
    int tx = tid & 15, ty = tid >> 4;       // tx: n-quad (4 cols), ty: m-octet (8 rows)
    int lr = tid >> 1, lk8 = (tid & 1) * 8; // loader: row, k-offset(8)

    ull acc[4][4];                           // [m-pair][n]
#pragma unroll
    for (int p = 0; p < 4; p++)
#pragma unroll
        for (int n = 0; n < 4; n++) acc[p][n] = 0ull;

    int colp_l = nbase + lr;
    int grow_l = (colp_l & 3) * 256 + (colp_l >> 2);
    int va = mbase + lr;

    for (int kb = 0; kb < DIN; kb += 16) {
#pragma unroll
        for (int h = 0; h < 2; h++) {
            int lk = lk8 + h * 4;
            float4 av = make_float4(0.f, 0.f, 0.f, 0.f);
            if (va < NDICT) av = *(const float4*)&Emb[(size_t)va * DIN + kb + lk];
            As[lk + 0][lr] = av.x; As[lk + 1][lr] = av.y;
            As[lk + 2][lr] = av.z; As[lk + 3][lr] = av.w;
            float4 bv = *(const float4*)&W[(size_t)grow_l * DIN + kb + lk];
            Bs[lk + 0][lr] = bv.x; Bs[lk + 1][lr] = bv.y;
            Bs[lk + 2][lr] = bv.z; Bs[lk + 3][lr] = bv.w;
        }
        __syncthreads();
#pragma unroll
        for (int kk = 0; kk < 16; kk++) {
            ulonglong2 aA = *(const ulonglong2*)&As[kk][ty * 8];      // (m0,m1),(m2,m3)
            ulonglong2 aB = *(const ulonglong2*)&As[kk][ty * 8 + 4];  // (m4,m5),(m6,m7)
            float4 b4 = *(const float4*)&Bs[kk][tx * 4];
            ull u0 = pk(b4.x, b4.x), u1 = pk(b4.y, b4.y);
            ull u2 = pk(b4.z, b4.z), u3 = pk(b4.w, b4.w);
            fma2(acc[0][0], aA.x, u0); fma2(acc[0][1], aA.x, u1);
            fma2(acc[0][2], aA.x, u2); fma2(acc[0][3], aA.x, u3);
            fma2(acc[1][0], aA.y, u0); fma2(acc[1][1], aA.y, u1);
            fma2(acc[1][2], aA.y, u2); fma2(acc[1][3], aA.y, u3);
            fma2(acc[2][0], aB.x, u0); fma2(acc[2][1], aB.x, u1);
            fma2(acc[2][2], aB.x, u2); fma2(acc[2][3], aB.x, u3);
            fma2(acc[3][0], aB.y, u0); fma2(acc[3][1], aB.y, u1);
            fma2(acc[3][2], aB.y, u2); fma2(acc[3][3], aB.y, u3);
        }
        __syncthreads();
    }

    int colp0 = nbase + tx * 4;
    int jj = colp0 >> 2;
    float bi = bias[jj], bf = bias[256 + jj], bo = bias[512 + jj], bc = bias[768 + jj];
#pragma unroll
    for (int p = 0; p < 4; p++) {
        float g0l, g0h, g1l, g1h, g2l, g2h, g3l, g3h;
        upk(acc[p][0], g0l, g0h); upk(acc[p][1], g1l, g1h);
        upk(acc[p][2], g2l, g2h); upk(acc[p][3], g3l, g3h);
        int v0 = mbase + ty * 8 + 2 * p;
        if (v0 < NDICT)
            *(float4*)&g_EW[(size_t)v0 * NGATE + colp0] =
                make_float4(g0l + bi, g1l + bf, g2l + bo, g3l + bc);
        if (v0 + 1 < NDICT)
            *(float4*)&g_EW[(size_t)(v0 + 1) * NGATE + colp0] =
                make_float4(g0h + bi, g1h + bf, g2h + bo, g3h + bc);
    }
}

// ---------------- kernel 2: persistent bidirectional LSTM scan ----------------
// grid = 128 CTAs: dir(2) x batch-tile(8, 32 rows) x gate-slice(8, 32 j / 128 cols)
// 128 threads, thread tile = 8 batch rows (4 f32x2 pairs) x 4 gate cols (one j)
__global__ __launch_bounds__(128, 1) void scan_kernel(const float* __restrict__ U) {
    extern __shared__ float sm[];
    float* hs = sm;                 // [256 k][32 b]  un-duplicated
    float* Us = sm + HS_FLOATS;     // [256 k][128 permuted gate cols]

    int tid = threadIdx.x;
    int bx = blockIdx.x;
    int dir = bx >> 6;
    int bt  = (bx >> 3) & 7;
    int js  = bx & 7;
    int grp = bx >> 3;                      // (dir,bt) group, 16 groups of 8 CTAs
    int tx = tid & 31, ty = tid >> 5;       // tx: j within slice; ty: batch octet
    int j = js * 32 + tx;
    int bbase = bt * 32 + ty * 8;

    // preload U slice: Us[k][col] = U[type*256 + js*32 + jl][k], col = jl*4+type
    for (int i = tid; i < 128 * 256; i += 128) {
        int col = i >> 8, k = i & 255;
        int type = col & 3, jl = col >> 2;
        Us[k * US_PITCH + col] = U[(size_t)(type * 256 + js * 32 + jl) * DH + k];
    }

    float c[8];
#pragma unroll
    for (int r = 0; r < 8; r++) c[r] = 0.f;
    __syncthreads();

    for (int t = 0; t < SS; t++) {
        int cur = t & 1, nxt = cur ^ 1;
        int s = dir ? (SS - 1 - t) : t;

        // prefetch EW rows (input gates + bias) early — covers DRAM latency
        float4 e[8];
#pragma unroll
        for (int r = 0; r < 8; r++) {
            int w = g_wordsT[s * BB + bbase + r];
            e[r] = __ldg((const float4*)&g_EW[(size_t)w * NGATE + j * 4]);
        }

        // stage h(t) [256 k][32 b] into smem (no duplication)
        const float* hsrc = g_h + (size_t)(cur * 2 + dir) * DH * BB + bt * 32;
#pragma unroll
        for (int it = 0; it < 16; it++) {
            int i = tid + it * 128;
            int k = i >> 3, b4 = (i & 7) << 2;
            float4 v = __ldcg((const float4*)&hsrc[k * BB + b4]);
            *(float4*)&hs[k * HS_PITCH + b4] = v;
        }
        __syncthreads();

        // gates tile: 4 batch-pairs x 4 gate types, batch-paired f32x2
        ull a0[4], a1[4], a2[4], a3[4];     // a{bp}[type]
#pragma unroll
        for (int n = 0; n < 4; n++) { a0[n] = 0; a1[n] = 0; a2[n] = 0; a3[n] = 0; }

        const float* hp = hs + ty * 8;
        const float* up = Us + tx * 4;
#pragma unroll 4
        for (int k = 0; k < 256; k++) {
            ulonglong2 hA = *(const ulonglong2*)(hp);      // (b0,b1),(b2,b3)
            ulonglong2 hB = *(const ulonglong2*)(hp + 4);  // (b4,b5),(b6,b7)
            float4 uv = *(const float4*)(up);
            ull u0 = pk(uv.x, uv.x), u1 = pk(uv.y, uv.y);
            ull u2 = pk(uv.z, uv.z), u3 = pk(uv.w, uv.w);
            fma2(a0[0], hA.x, u0); fma2(a0[1], hA.x, u1);
            fma2(a0[2], hA.x, u2); fma2(a0[3], hA.x, u3);
            fma2(a1[0], hA.y, u0); fma2(a1[1], hA.y, u1);
            fma2(a1[2], hA.y, u2); fma2(a1[3], hA.y, u3);
            fma2(a2[0], hB.x, u0); fma2(a2[1], hB.x, u1);
            fma2(a2[2], hB.x, u2); fma2(a2[3], hB.x, u3);
            fma2(a3[0], hB.y, u0); fma2(a3[1], hB.y, u1);
            fma2(a3[2], hB.y, u2); fma2(a3[3], hB.y, u3);
            hp += HS_PITCH; up += US_PITCH;
        }

        // epilogue: unpack pairs, activations, c update
        float hout[8];
#pragma unroll
        for (int bp = 0; bp < 4; bp++) {
            const ull* ap = (bp == 0) ? a0 : (bp == 1) ? a1 : (bp == 2) ? a2 : a3;
            float gil, gih, gfl, gfh, gol, goh, gcl, gch;
            upk(ap[0], gil, gih); upk(ap[1], gfl, gfh);
            upk(ap[2], gol, goh); upk(ap[3], gcl, gch);
            int r0 = 2 * bp, r1 = 2 * bp + 1;
            {
                float gi = fsig(gil + e[r0].x), gf = fsig(gfl + e[r0].y);
                float go = fsig(gol + e[r0].z), gc = ftanh(gcl + e[r0].w);
                c[r0] = gf * c[r0] + gi * gc;
                hout[r0] = go * ftanh(c[r0]);
            }
            {
                float gi = fsig(gih + e[r1].x), gf = fsig(gfh + e[r1].y);
                float go = fsig(goh + e[r1].z), gc = ftanh(gch + e[r1].w);
                c[r1] = gf * c[r1] + gi * gc;
                hout[r1] = go * ftanh(c[r1]);
            }
        }
        float* hdst = g_h + (size_t)((nxt * 2 + dir) * DH + j) * BB + bbase;
        __stcg((float4*)hdst, make_float4(hout[0], hout[1], hout[2], hout[3]));
        __stcg((float4*)(hdst + 4), make_float4(hout[4], hout[5], hout[6], hout[7]));

        __syncthreads();   // all hs reads done, all h stores issued
        if (t < SS - 1) {
            if (tid == 0) {
                asm volatile("st.release.gpu.u32 [%0], %1;"
                             :: "l"(&g_flags[grp * 64 + js * 8]), "r"(t + 1) : "memory");
            }
            if (tid < 8) {  // poll only this group's 8 flags
                unsigned* fp = &g_flags[grp * 64 + tid * 8];
                unsigned v;
                do {
                    asm volatile("ld.acquire.gpu.u32 %0, [%1];"
                                 : "=r"(v) : "l"(fp) : "memory");
                } while ((int)v < t + 1);
            }
            __syncthreads();
        }
    }
}

// ---------------- kernel 3: output layer (one block per batch row) ----------------
__global__ void out_kernel(const float* __restrict__ outW,
                           const float* __restrict__ outb,
                           float* __restrict__ pred) {
    int b = blockIdx.x;
    int tid = threadIdx.x;  // 128 threads
    const float* hl = g_h;                       // buf0 dir0 [j][b]
    const float* hr = g_h + (size_t)DH * BB;     // buf0 dir1
    float a0 = 0.f, a1 = 0.f;
    for (int idx = tid; idx < 512; idx += 128) {
        float v = (idx < 256) ? hl[idx * BB + b] : hr[(idx - 256) * BB + b];
        a0 += v * outW[idx];
        a1 += v * outW[512 + idx];
    }
#pragma unroll
    for (int o = 16; o > 0; o >>= 1) {
        a0 += __shfl_down_sync(0xFFFFFFFFu, a0, o);
        a1 += __shfl_down_sync(0xFFFFFFFFu, a1, o);
    }
    __shared__ float s0[4], s1[4];
    if ((tid & 31) == 0) { s0[tid >> 5] = a0; s1[tid >> 5] = a1; }
    __syncthreads();
    if (tid == 0) {
        pred[b * 2 + 0] = s0[0] + s0[1] + s0[2] + s0[3] + outb[0];
        pred[b * 2 + 1] = s1[0] + s1[1] + s1[2] + s1[3] + outb[1];
    }
}

// ---------------- launch ----------------
extern "C" void kernel_launch(void* const* d_in, const int* in_sizes, int n_in,
                              void* d_out, int out_size) {
    const int*   words = (const int*)d_in[0];
    const float* Emb   = (const float*)d_in[1];
    const float* W     = (const float*)d_in[2];
    const float* U     = (const float*)d_in[3];
    const float* bias  = (const float*)d_in[4];
    const float* outW  = (const float*)d_in[5];
    const float* outb  = (const float*)d_in[6];
    float* pred = (float*)d_out;

    cudaFuncSetAttribute(scan_kernel, cudaFuncAttributeMaxDynamicSharedMemorySize, SCAN_SMEM);

    reset_kernel<<<256, 256>>>(words);
    ew_gemm<<<dim3((NDICT + 63) / 64, NGATE / 64), 128>>>(Emb, W, bias);
    scan_kernel<<<NBLK, 128, SCAN_SMEM>>>(U);
    out_kernel<<<256, 128>>>(outW, outb, pred);
}

// round 6
// speedup vs baseline: 1.9074x; 1.4365x over previous
#include <cuda_runtime.h>
#include <cuda_bf16.h>
#include <cstdint>

typedef unsigned long long ull;
typedef unsigned int u32;

// ---------------- constants ----------------
#define NDICT   50000
#define DIN     256
#define DH      256
#define NGATE   1024
#define BB      256
#define SS      512
#define NBLK    128

// scan smem layout (bytes); pitches chosen for conflict-free ldmatrix
#define AP 264                      // U row pitch in bf16 (33 x 16B granules)
#define HP 264                      // h row pitch in bf16
#define GP 34                       // gates pitch in floats (even -> float2 ok)
#define SM_UHI   0
#define SM_ULO   (SM_UHI + 128 * AP * 2)          // 67584
#define SM_HHI   (SM_ULO + 128 * AP * 2)          // 135168
#define SM_HLO   (SM_HHI + 32 * HP * 2)           // 152064
#define SM_GATES (SM_HLO + 32 * HP * 2)           // 168960
#define SM_TOTAL (SM_GATES + 128 * GP * 4)        // 186368 B

// ---------------- device scratch ----------------
__device__ float g_EW[(size_t)NDICT * NGATE];  // Emb@W^T + bias, cols permuted j*4+type
__device__ u32   g_hsplit[2 * 2 * BB * DH];    // [buf][dir][b][k] packed bf16 hi | lo<<16
__device__ float g_h[2 * DH * BB];             // final h [dir][j][b] fp32
__device__ int   g_wordsT[SS * BB];
__device__ unsigned g_flags[16 * 64];          // [group][js*8]

// ---------------- helpers ----------------
__device__ __forceinline__ u32 smem_u32(const void* p) {
    u32 a; asm("{ .reg .u64 t; cvta.to.shared.u64 t, %1; cvt.u32.u64 %0, t; }"
               : "=r"(a) : "l"(p));
    return a;
}
__device__ __forceinline__ float fsig(float x) {
    float e = __expf(-x);
    return __fdividef(1.0f, 1.0f + e);
}
__device__ __forceinline__ float ftanh(float x) {
    float ax = fabsf(x);
    float e  = __expf(-2.0f * ax);
    float r  = __fdividef(1.0f - e, 1.0f + e);
    return copysignf(r, x);
}
__device__ __forceinline__ ull pkf(float x, float y) {
    ull r; asm("mov.b64 %0, {%1, %2};" : "=l"(r) : "f"(x), "f"(y)); return r;
}
__device__ __forceinline__ void upkf(ull v, float& x, float& y) {
    asm("mov.b64 {%0, %1}, %2;" : "=f"(x), "=f"(y) : "l"(v));
}
__device__ __forceinline__ void fma2(ull& d, ull a, ull b) {
    asm("fma.rn.f32x2 %0, %1, %2, %0;" : "+l"(d) : "l"(a), "l"(b));
}
__device__ __forceinline__ void ldsm4(u32* r, u32 addr) {
    asm volatile("ldmatrix.sync.aligned.m8n8.x4.shared.b16 {%0,%1,%2,%3}, [%4];"
                 : "=r"(r[0]), "=r"(r[1]), "=r"(r[2]), "=r"(r[3]) : "r"(addr));
}
__device__ __forceinline__ void mma16816(float* c, const u32* a, const u32* b) {
    asm volatile("mma.sync.aligned.m16n8k16.row.col.f32.bf16.bf16.f32 "
                 "{%0,%1,%2,%3}, {%4,%5,%6,%7}, {%8,%9}, {%0,%1,%2,%3};"
                 : "+f"(c[0]), "+f"(c[1]), "+f"(c[2]), "+f"(c[3])
                 : "r"(a[0]), "r"(a[1]), "r"(a[2]), "r"(a[3]), "r"(b[0]), "r"(b[1]));
}

// ---------------- kernel 0: reset ----------------
__global__ void reset_kernel(const int* __restrict__ words) {
    int idx = blockIdx.x * blockDim.x + threadIdx.x;
    if (idx < 16 * 64) g_flags[idx] = 0u;
    for (int i = idx; i < 2 * BB * DH; i += gridDim.x * blockDim.x) g_hsplit[i] = 0u;
    for (int i = idx; i < SS * BB; i += gridDim.x * blockDim.x) {
        int s = i >> 8, b = i & 255;
        g_wordsT[i] = words[b * SS + s];
    }
}

// ---------------- kernel 1: EW = Emb @ W^T (+bias), columns permuted ----------------
__global__ __launch_bounds__(128) void ew_gemm(const float* __restrict__ Emb,
                                               const float* __restrict__ W,
                                               const float* __restrict__ bias) {
    __shared__ __align__(16) float As[16][68];
    __shared__ __align__(16) float Bs[16][68];
    int tid = threadIdx.x;
    int mbase = blockIdx.x * 64;
    int nbase = blockIdx.y * 64;
    int tx = tid & 15, ty = tid >> 4;
    int lr = tid >> 1, lk8 = (tid & 1) * 8;

    ull acc[4][4];
#pragma unroll
    for (int p = 0; p < 4; p++)
#pragma unroll
        for (int n = 0; n < 4; n++) acc[p][n] = 0ull;

    int colp_l = nbase + lr;
    int grow_l = (colp_l & 3) * 256 + (colp_l >> 2);
    int va = mbase + lr;

    for (int kb = 0; kb < DIN; kb += 16) {
#pragma unroll
        for (int h = 0; h < 2; h++) {
            int lk = lk8 + h * 4;
            float4 av = make_float4(0.f, 0.f, 0.f, 0.f);
            if (va < NDICT) av = *(const float4*)&Emb[(size_t)va * DIN + kb + lk];
            As[lk + 0][lr] = av.x; As[lk + 1][lr] = av.y;
            As[lk + 2][lr] = av.z; As[lk + 3][lr] = av.w;
            float4 bv = *(const float4*)&W[(size_t)grow_l * DIN + kb + lk];
            Bs[lk + 0][lr] = bv.x; Bs[lk + 1][lr] = bv.y;
            Bs[lk + 2][lr] = bv.z; Bs[lk + 3][lr] = bv.w;
        }
        __syncthreads();
#pragma unroll
        for (int kk = 0; kk < 16; kk++) {
            ulonglong2 aA = *(const ulonglong2*)&As[kk][ty * 8];
            ulonglong2 aB = *(const ulonglong2*)&As[kk][ty * 8 + 4];
            float4 b4 = *(const float4*)&Bs[kk][tx * 4];
            ull u0 = pkf(b4.x, b4.x), u1 = pkf(b4.y, b4.y);
            ull u2 = pkf(b4.z, b4.z), u3 = pkf(b4.w, b4.w);
            fma2(acc[0][0], aA.x, u0); fma2(acc[0][1], aA.x, u1);
            fma2(acc[0][2], aA.x, u2); fma2(acc[0][3], aA.x, u3);
            fma2(acc[1][0], aA.y, u0); fma2(acc[1][1], aA.y, u1);
            fma2(acc[1][2], aA.y, u2); fma2(acc[1][3], aA.y, u3);
            fma2(acc[2][0], aB.x, u0); fma2(acc[2][1], aB.x, u1);
            fma2(acc[2][2], aB.x, u2); fma2(acc[2][3], aB.x, u3);
            fma2(acc[3][0], aB.y, u0); fma2(acc[3][1], aB.y, u1);
            fma2(acc[3][2], aB.y, u2); fma2(acc[3][3], aB.y, u3);
        }
        __syncthreads();
    }

    int colp0 = nbase + tx * 4;
    int jj = colp0 >> 2;
    float bi = bias[jj], bf = bias[256 + jj], bo = bias[512 + jj], bc = bias[768 + jj];
#pragma unroll
    for (int p = 0; p < 4; p++) {
        float g0l, g0h, g1l, g1h, g2l, g2h, g3l, g3h;
        upkf(acc[p][0], g0l, g0h); upkf(acc[p][1], g1l, g1h);
        upkf(acc[p][2], g2l, g2h); upkf(acc[p][3], g3l, g3h);
        int v0 = mbase + ty * 8 + 2 * p;
        if (v0 < NDICT)
            *(float4*)&g_EW[(size_t)v0 * NGATE + colp0] =
                make_float4(g0l + bi, g1l + bf, g2l + bo, g3l + bc);
        if (v0 + 1 < NDICT)
            *(float4*)&g_EW[(size_t)(v0 + 1) * NGATE + colp0] =
                make_float4(g0h + bi, g1h + bf, g2h + bo, g3h + bc);
    }
}

// ---------------- kernel 2: persistent scan — split-bf16 mma.sync ----------------
// grid = 128 CTAs: dir(2) x batch-tile(8, 32 rows) x gate-slice(8, 32 j)
// Per CTA-step: gates[128 rows(type*32+jl), 32 batch] = U.h via 3 split passes
__global__ __launch_bounds__(128, 1) void scan_kernel(const float* __restrict__ U) {
    extern __shared__ __align__(16) char smem[];
    u32 sbase = smem_u32(smem);
    float* gates_sm = (float*)(smem + SM_GATES);

    int tid = threadIdx.x;
    int w = tid >> 5, lid = tid & 31;
    int bx = blockIdx.x;
    int dir = bx >> 6;
    int bt  = (bx >> 3) & 7;
    int js  = bx & 7;
    int grp = bx >> 3;
    int tx = tid & 31, ty = tid >> 5;       // epilogue: tx = j in slice, ty = batch octet
    int j = js * 32 + tx;
    int bbase = bt * 32 + ty * 8;

    // ---- preload U slice as split bf16: rows r = type*32+jl, pitch AP
    for (int i = tid; i < 128 * 256; i += 128) {
        int r = i >> 8, k = i & 255;
        int type = r >> 5, jl = r & 31;
        float u = U[(size_t)(type * 256 + js * 32 + jl) * DH + k];
        __nv_bfloat16 hi = __float2bfloat16(u);
        __nv_bfloat16 lo = __float2bfloat16(u - __bfloat162float(hi));
        *(__nv_bfloat16*)(smem + SM_UHI + (r * AP + k) * 2) = hi;
        *(__nv_bfloat16*)(smem + SM_ULO + (r * AP + k) * 2) = lo;
    }

    // ldmatrix per-thread address offsets (conflict-free: pitch 33 x 16B)
    int idx = lid >> 3, r8 = lid & 7;
    u32 aoff0 = (u32)(((w * 32 + (idx & 1) * 8 + r8) * AP + (idx >> 1) * 8) * 2);
    u32 aoff1 = aoff0 + (u32)(16 * AP * 2);
    u32 boff0 = (u32)((((idx >> 1) * 8 + r8) * HP + (idx & 1) * 8) * 2);
    u32 boff1 = boff0 + (u32)(16 * HP * 2);

    float c[8];
#pragma unroll
    for (int r = 0; r < 8; r++) c[r] = 0.f;
    __syncthreads();

    for (int t = 0; t < SS; t++) {
        int cur = t & 1, nxt = cur ^ 1;
        int s = dir ? (SS - 1 - t) : t;

        // EW prefetch (independent; latency hidden under staging + MMA)
        float4 e[8];
#pragma unroll
        for (int r = 0; r < 8; r++) {
            int wd = g_wordsT[s * BB + bbase + r];
            e[r] = __ldg((const float4*)&g_EW[(size_t)wd * NGATE + j * 4]);
        }

        // ---- stage h(t) hi/lo [32 b x 256 k] bf16, pitch HP
        {
            const uint4* hb = (const uint4*)(g_hsplit + ((size_t)(cur * 2 + dir) * BB + bt * 32) * DH);
#pragma unroll
            for (int it = 0; it < 4; it++) {
                int i = tid + it * 128;
                int b = i >> 4, c4 = (i & 15) * 4;     // 4 uint4 per thread-slot? no: c4 index
                // each iteration handles one uint4 = 4 k; 32 b x 64 uint4 = 2048 slots / 128 = 16
                (void)b; (void)c4;
            }
#pragma unroll
            for (int it = 0; it < 16; it++) {
                int i = tid + it * 128;
                int b = i >> 6, c4 = i & 63;
                uint4 v = __ldcg(hb + b * 64 + c4);
                u32 hi0 = __byte_perm(v.x, v.y, 0x5410);
                u32 hi1 = __byte_perm(v.z, v.w, 0x5410);
                u32 lo0 = __byte_perm(v.x, v.y, 0x7632);
                u32 lo1 = __byte_perm(v.z, v.w, 0x7632);
                int k0 = c4 * 4;
                *(ull*)(smem + SM_HHI + (b * HP + k0) * 2) = (ull)hi0 | ((ull)hi1 << 32);
                *(ull*)(smem + SM_HLO + (b * HP + k0) * 2) = (ull)lo0 | ((ull)lo1 << 32);
            }
        }
        __syncthreads();

        // ---- 3-pass split-bf16 MMA: each warp 32 gate rows x 32 batch, K=256
        float acc[2][4][4];
#pragma unroll
        for (int mt = 0; mt < 2; mt++)
#pragma unroll
            for (int nt = 0; nt < 4; nt++)
#pragma unroll
                for (int q = 0; q < 4; q++) acc[mt][nt][q] = 0.f;

#pragma unroll
        for (int pass = 0; pass < 3; pass++) {
            u32 abase = sbase + (pass == 2 ? SM_ULO : SM_UHI);
            u32 bbase2 = sbase + (pass == 1 ? SM_HLO : SM_HHI);
#pragma unroll
            for (int kt = 0; kt < 16; kt++) {
                u32 koff = (u32)(kt * 32);
                u32 af0[4], af1[4], bf[8];
                ldsm4(af0, abase + aoff0 + koff);
                ldsm4(af1, abase + aoff1 + koff);
                ldsm4(bf,     bbase2 + boff0 + koff);
                ldsm4(bf + 4, bbase2 + boff1 + koff);
                mma16816(acc[0][0], af0, bf + 0);
                mma16816(acc[0][1], af0, bf + 2);
                mma16816(acc[0][2], af0, bf + 4);
                mma16816(acc[0][3], af0, bf + 6);
                mma16816(acc[1][0], af1, bf + 0);
                mma16816(acc[1][1], af1, bf + 2);
                mma16816(acc[1][2], af1, bf + 4);
                mma16816(acc[1][3], af1, bf + 6);
            }
        }

        // ---- write gates to smem (fragment layout -> [row][batch], pitch GP)
#pragma unroll
        for (int mt = 0; mt < 2; mt++) {
#pragma unroll
            for (int nt = 0; nt < 4; nt++) {
                int row0 = w * 32 + mt * 16 + (lid >> 2);
                int col = nt * 8 + (lid & 3) * 2;
                *(float2*)&gates_sm[row0 * GP + col] =
                    make_float2(acc[mt][nt][0], acc[mt][nt][1]);
                *(float2*)&gates_sm[(row0 + 8) * GP + col] =
                    make_float2(acc[mt][nt][2], acc[mt][nt][3]);
            }
        }
        __syncthreads();

        // ---- epilogue: per (j, 8 batches) activations + c update
        float hout[8];
#pragma unroll
        for (int r = 0; r < 8; r++) {
            int b = ty * 8 + r;
            float gi = gates_sm[(0 * 32 + tx) * GP + b] + e[r].x;
            float gf = gates_sm[(1 * 32 + tx) * GP + b] + e[r].y;
            float go = gates_sm[(2 * 32 + tx) * GP + b] + e[r].z;
            float gc = gates_sm[(3 * 32 + tx) * GP + b] + e[r].w;
            gi = fsig(gi); gf = fsig(gf); go = fsig(go); gc = ftanh(gc);
            c[r] = gf * c[r] + gi * gc;
            hout[r] = go * ftanh(c[r]);
        }
        // pack h -> bf16 hi|lo u32, store to global
        u32* hdst = g_hsplit + ((size_t)(nxt * 2 + dir) * BB + bbase) * DH + j;
#pragma unroll
        for (int r = 0; r < 8; r++) {
            __nv_bfloat16 hi = __float2bfloat16(hout[r]);
            __nv_bfloat16 lo = __float2bfloat16(hout[r] - __bfloat162float(hi));
            u32 pkv = (u32)__bfloat16_as_ushort(hi) | ((u32)__bfloat16_as_ushort(lo) << 16);
            __stcg(hdst + (size_t)r * DH, pkv);
        }
        if (t == SS - 1) {
#pragma unroll
            for (int r = 0; r < 8; r++)
                g_h[(size_t)dir * DH * BB + (size_t)j * BB + bbase + r] = hout[r];
        }

        __syncthreads();
        if (t < SS - 1) {
            if (tid == 0) {
                asm volatile("st.release.gpu.u32 [%0], %1;"
                             :: "l"(&g_flags[grp * 64 + js * 8]), "r"(t + 1) : "memory");
            }
            if (tid < 8) {
                unsigned* fp = &g_flags[grp * 64 + tid * 8];
                unsigned v;
                do {
                    asm volatile("ld.acquire.gpu.u32 %0, [%1];"
                                 : "=r"(v) : "l"(fp) : "memory");
                } while ((int)v < t + 1);
            }
            __syncthreads();
        }
    }
}

// ---------------- kernel 3: output layer ----------------
__global__ void out_kernel(const float* __restrict__ outW,
                           const float* __restrict__ outb,
                           float* __restrict__ pred) {
    int b = blockIdx.x;
    int tid = threadIdx.x;
    const float* hl = g_h;
    const float* hr = g_h + (size_t)DH * BB;
    float a0 = 0.f, a1 = 0.f;
    for (int idx = tid; idx < 512; idx += 128) {
        float v = (idx < 256) ? hl[idx * BB + b] : hr[(idx - 256) * BB + b];
        a0 += v * outW[idx];
        a1 += v * outW[512 + idx];
    }
#pragma unroll
    for (int o = 16; o > 0; o >>= 1) {
        a0 += __shfl_down_sync(0xFFFFFFFFu, a0, o);
        a1 += __shfl_down_sync(0xFFFFFFFFu, a1, o);
    }
    __shared__ float s0[4], s1[4];
    if ((tid & 31) == 0) { s0[tid >> 5] = a0; s1[tid >> 5] = a1; }
    __syncthreads();
    if (tid == 0) {
        pred[b * 2 + 0] = s0[0] + s0[1] + s0[2] + s0[3] + outb[0];
        pred[b * 2 + 1] = s1[0] + s1[1] + s1[2] + s1[3] + outb[1];
    }
}

// ---------------- launch ----------------
extern "C" void kernel_launch(void* const* d_in, const int* in_sizes, int n_in,
                              void* d_out, int out_size) {
    const int*   words = (const int*)d_in[0];
    const float* Emb   = (const float*)d_in[1];
    const float* W     = (const float*)d_in[2];
    const float* U     = (const float*)d_in[3];
    const float* bias  = (const float*)d_in[4];
    const float* outW  = (const float*)d_in[5];
    const float* outb  = (const float*)d_in[6];
    float* pred = (float*)d_out;

    cudaFuncSetAttribute(scan_kernel, cudaFuncAttributeMaxDynamicSharedMemorySize, SM_TOTAL);

    reset_kernel<<<256, 256>>>(words);
    ew_gemm<<<dim3((NDICT + 63) / 64, NGATE / 64), 128>>>(Emb, W, bias);
    scan_kernel<<<NBLK, 128, SM_TOTAL>>>(U);
    out_kernel<<<256, 128>>>(outW, outb, pred);
}

// round 7
// speedup vs baseline: 2.5011x; 1.3113x over previous
#include <cuda_runtime.h>
#include <cuda_bf16.h>
#include <cstdint>

typedef unsigned long long ull;
typedef unsigned int u32;
typedef unsigned short u16;

// ---------------- constants ----------------
#define NDICT   50000
#define DIN     256
#define DH      256
#define NGATE   1024
#define BB      256
#define SS      512
#define NBLK    128

// ---- scan smem (bytes); pitches conflict-free for ldmatrix
#define AP 264                      // U row pitch in bf16 (33 x 16B)
#define HP 264                      // h row pitch in bf16
#define GP 34                       // gates pitch in floats
#define SM_UHI   0
#define SM_HHI   (SM_UHI + 128 * AP * 2)          // 67584
#define SM_HLO   (SM_HHI + 32 * HP * 2)           // 84480
#define SM_GATES (SM_HLO + 32 * HP * 2)           // 101376
#define SM_TOTAL (SM_GATES + 128 * GP * 4)        // 118784 B

// ---- ew_gemm2 smem (bytes); pitch 72 bf16 = 144 B
#define EP 72
#define EW_AH 0
#define EW_AL (EW_AH + 128 * EP * 2)              // 18432
#define EW_BH (EW_AL + 128 * EP * 2)              // 36864
#define EW_BL (EW_BH + 128 * EP * 2)              // 55296
#define EW_BIAS (EW_BL + 128 * EP * 2)            // 73728
#define EW_SMEM (EW_BIAS + 128 * 4)               // 74240 B

// ---------------- device scratch ----------------
__device__ float g_EW[(size_t)NDICT * NGATE];  // Emb@W^T + bias, cols permuted j*4+type
__device__ u32   g_hsplit[2 * 2 * BB * DH];    // [buf][dir][b][k] packed bf16 hi | lo<<16
__device__ float g_h[2 * DH * BB];             // final h [dir][j][b] fp32
__device__ int   g_wordsT[SS * BB];
__device__ unsigned g_flags[16 * 64];          // [group][js*8]

// ---------------- helpers ----------------
__device__ __forceinline__ u32 smem_u32(const void* p) {
    u32 a; asm("{ .reg .u64 t; cvta.to.shared.u64 t, %1; cvt.u32.u64 %0, t; }"
               : "=r"(a) : "l"(p));
    return a;
}
__device__ __forceinline__ float fsig(float x) {
    float e = __expf(-x);
    return __fdividef(1.0f, 1.0f + e);
}
__device__ __forceinline__ float ftanh(float x) {
    float ax = fabsf(x);
    float e  = __expf(-2.0f * ax);
    float r  = __fdividef(1.0f - e, 1.0f + e);
    return copysignf(r, x);
}
__device__ __forceinline__ void ldsm4(u32* r, u32 addr) {
    asm volatile("ldmatrix.sync.aligned.m8n8.x4.shared.b16 {%0,%1,%2,%3}, [%4];"
                 : "=r"(r[0]), "=r"(r[1]), "=r"(r[2]), "=r"(r[3]) : "r"(addr));
}
__device__ __forceinline__ void mma16816(float* c, const u32* a, const u32* b) {
    asm volatile("mma.sync.aligned.m16n8k16.row.col.f32.bf16.bf16.f32 "
                 "{%0,%1,%2,%3}, {%4,%5,%6,%7}, {%8,%9}, {%0,%1,%2,%3};"
                 : "+f"(c[0]), "+f"(c[1]), "+f"(c[2]), "+f"(c[3])
                 : "r"(a[0]), "r"(a[1]), "r"(a[2]), "r"(a[3]), "r"(b[0]), "r"(b[1]));
}
// split a float into bf16 hi + bf16 lo
__device__ __forceinline__ void bsplit(float x, u16& hi, u16& lo) {
    __nv_bfloat16 h = __float2bfloat16(x);
    __nv_bfloat16 l = __float2bfloat16(x - __bfloat162float(h));
    hi = __bfloat16_as_ushort(h);
    lo = __bfloat16_as_ushort(l);
}

// ---------------- kernel 0: reset ----------------
__global__ void reset_kernel(const int* __restrict__ words) {
    int idx = blockIdx.x * blockDim.x + threadIdx.x;
    if (idx < 16 * 64) g_flags[idx] = 0u;
    for (int i = idx; i < 2 * BB * DH; i += gridDim.x * blockDim.x) g_hsplit[i] = 0u;
    for (int i = idx; i < SS * BB; i += gridDim.x * blockDim.x) {
        int s = i >> 8, b = i & 255;
        g_wordsT[i] = words[b * SS + s];
    }
}

// ---------------- kernel 1: EW = Emb @ W^T (+bias), split-bf16 HMMA ----------------
// grid (391, 8), 256 thr = 8 warps (4m x 2n), CTA tile 128m x 128n, K=256 in 4 chunks
__global__ __launch_bounds__(256) void ew_gemm2(const float* __restrict__ Emb,
                                                const float* __restrict__ W,
                                                const float* __restrict__ bias) {
    extern __shared__ __align__(16) char esm[];
    u32 sb = smem_u32(esm);
    float* biasp = (float*)(esm + EW_BIAS);

    int tid = threadIdx.x;
    int w = tid >> 5, lid = tid & 31;
    int mbase = blockIdx.x * 128;
    int nbase = blockIdx.y * 128;
    int wm = (w & 3) * 32, wn = (w >> 2) * 64;

    if (tid < 128) {
        int colp = nbase + tid;
        biasp[tid] = bias[(colp & 3) * 256 + (colp >> 2)];
    }

    // fragment smem offsets (bytes)
    int idx4 = lid >> 3, r8 = lid & 7;
    u32 aoff0 = (u32)(((wm + (idx4 & 1) * 8 + r8) * EP + (idx4 >> 1) * 8) * 2);
    u32 aoff1 = aoff0 + (u32)(16 * EP * 2);
    u32 boffB = (u32)(((wn + (idx4 >> 1) * 8 + r8) * EP + (idx4 & 1) * 8) * 2);

    float acc[2][8][4];
#pragma unroll
    for (int mt = 0; mt < 2; mt++)
#pragma unroll
        for (int n8 = 0; n8 < 8; n8++)
#pragma unroll
            for (int q = 0; q < 4; q++) acc[mt][n8][q] = 0.f;

    for (int kb = 0; kb < 4; kb++) {
        int k0 = kb * 64;
        // stage A (Emb tile) 128 x 64 -> hi/lo bf16
        for (int i = tid; i < 128 * 16; i += 256) {
            int row = i >> 4, kq = (i & 15) * 4;
            int va = mbase + row;
            float4 v = make_float4(0.f, 0.f, 0.f, 0.f);
            if (va < NDICT) v = *(const float4*)&Emb[(size_t)va * DIN + k0 + kq];
            u16 h0, l0, h1, l1, h2, l2, h3, l3;
            bsplit(v.x, h0, l0); bsplit(v.y, h1, l1);
            bsplit(v.z, h2, l2); bsplit(v.w, h3, l3);
            u32* ah = (u32*)(esm + EW_AH + (row * EP + kq) * 2);
            u32* al = (u32*)(esm + EW_AL + (row * EP + kq) * 2);
            ah[0] = (u32)h0 | ((u32)h1 << 16); ah[1] = (u32)h2 | ((u32)h3 << 16);
            al[0] = (u32)l0 | ((u32)l1 << 16); al[1] = (u32)l2 | ((u32)l3 << 16);
        }
        // stage B (W tile, permuted rows) 128 x 64 -> hi/lo bf16
        for (int i = tid; i < 128 * 16; i += 256) {
            int row = i >> 4, kq = (i & 15) * 4;
            int colp = nbase + row;
            int grow = (colp & 3) * 256 + (colp >> 2);
            float4 v = *(const float4*)&W[(size_t)grow * DIN + k0 + kq];
            u16 h0, l0, h1, l1, h2, l2, h3, l3;
            bsplit(v.x, h0, l0); bsplit(v.y, h1, l1);
            bsplit(v.z, h2, l2); bsplit(v.w, h3, l3);
            u32* bh = (u32*)(esm + EW_BH + (row * EP + kq) * 2);
            u32* bl = (u32*)(esm + EW_BL + (row * EP + kq) * 2);
            bh[0] = (u32)h0 | ((u32)h1 << 16); bh[1] = (u32)h2 | ((u32)h3 << 16);
            bl[0] = (u32)l0 | ((u32)l1 << 16); bl[1] = (u32)l2 | ((u32)l3 << 16);
        }
        __syncthreads();

#pragma unroll
        for (int kt = 0; kt < 4; kt++) {
            u32 koff = (u32)(kt * 32);
            u32 a0h[4], a1h[4], a0l[4], a1l[4];
            ldsm4(a0h, sb + EW_AH + aoff0 + koff);
            ldsm4(a1h, sb + EW_AH + aoff1 + koff);
            ldsm4(a0l, sb + EW_AL + aoff0 + koff);
            ldsm4(a1l, sb + EW_AL + aoff1 + koff);
#pragma unroll
            for (int p = 0; p < 4; p++) {
                u32 po = (u32)(p * 16 * EP * 2);
                u32 bh[4], bl[4];
                ldsm4(bh, sb + EW_BH + boffB + po + koff);
                ldsm4(bl, sb + EW_BL + boffB + po + koff);
                mma16816(acc[0][2 * p + 0], a0h, bh + 0);
                mma16816(acc[0][2 * p + 1], a0h, bh + 2);
                mma16816(acc[1][2 * p + 0], a1h, bh + 0);
                mma16816(acc[1][2 * p + 1], a1h, bh + 2);
                mma16816(acc[0][2 * p + 0], a0h, bl + 0);
                mma16816(acc[0][2 * p + 1], a0h, bl + 2);
                mma16816(acc[1][2 * p + 0], a1h, bl + 0);
                mma16816(acc[1][2 * p + 1], a1h, bl + 2);
                mma16816(acc[0][2 * p + 0], a0l, bh + 0);
                mma16816(acc[0][2 * p + 1], a0l, bh + 2);
                mma16816(acc[1][2 * p + 0], a1l, bh + 0);
                mma16816(acc[1][2 * p + 1], a1l, bh + 2);
            }
        }
        __syncthreads();
    }

    // epilogue: add bias, store
#pragma unroll
    for (int mt = 0; mt < 2; mt++) {
#pragma unroll
        for (int n8 = 0; n8 < 8; n8++) {
            int nl = wn + n8 * 8 + (lid & 3) * 2;
            int col = nbase + nl;
            float b0 = biasp[nl], b1 = biasp[nl + 1];
            int r0 = mbase + wm + mt * 16 + (lid >> 2);
            if (r0 < NDICT)
                *(float2*)&g_EW[(size_t)r0 * NGATE + col] =
                    make_float2(acc[mt][n8][0] + b0, acc[mt][n8][1] + b1);
            if (r0 + 8 < NDICT)
                *(float2*)&g_EW[(size_t)(r0 + 8) * NGATE + col] =
                    make_float2(acc[mt][n8][2] + b0, acc[mt][n8][3] + b1);
        }
    }
}

// ---------------- kernel 2: persistent scan — 2-pass split-bf16 mma.sync ----------------
// grid = 128 CTAs: dir(2) x batch-tile(8, 32 rows) x gate-slice(8, 32 j)
// gates[128 rows(type*32+jl), 32 b] = Uhi.hhi + Uhi.hlo  (U rounded to bf16)
__global__ __launch_bounds__(128, 1) void scan_kernel(const float* __restrict__ U) {
    extern __shared__ __align__(16) char smem[];
    u32 sbase = smem_u32(smem);
    float* gates_sm = (float*)(smem + SM_GATES);

    int tid = threadIdx.x;
    int w = tid >> 5, lid = tid & 31;
    int bx = blockIdx.x;
    int dir = bx >> 6;
    int bt  = (bx >> 3) & 7;
    int js  = bx & 7;
    int grp = bx >> 3;
    int tx = tid & 31, ty = tid >> 5;
    int j = js * 32 + tx;
    int bbase = bt * 32 + ty * 8;

    // preload U slice rows r = type*32+jl (bf16 hi only), pitch AP
    for (int i = tid; i < 128 * 256; i += 128) {
        int r = i >> 8, k = i & 255;
        int type = r >> 5, jl = r & 31;
        float u = U[(size_t)(type * 256 + js * 32 + jl) * DH + k];
        *(__nv_bfloat16*)(smem + SM_UHI + (r * AP + k) * 2) = __float2bfloat16(u);
    }

    int idx4 = lid >> 3, r8 = lid & 7;
    u32 aoff0 = (u32)(((w * 32 + (idx4 & 1) * 8 + r8) * AP + (idx4 >> 1) * 8) * 2);
    u32 aoff1 = aoff0 + (u32)(16 * AP * 2);
    u32 boff0 = (u32)((((idx4 >> 1) * 8 + r8) * HP + (idx4 & 1) * 8) * 2);
    u32 boff1 = boff0 + (u32)(16 * HP * 2);

    float c[8];
#pragma unroll
    for (int r = 0; r < 8; r++) c[r] = 0.f;
    __syncthreads();

    for (int t = 0; t < SS; t++) {
        int cur = t & 1, nxt = cur ^ 1;
        int s = dir ? (SS - 1 - t) : t;

        // EW prefetch (hidden under staging + MMA)
        float4 e[8];
#pragma unroll
        for (int r = 0; r < 8; r++) {
            int wd = g_wordsT[s * BB + bbase + r];
            e[r] = __ldg((const float4*)&g_EW[(size_t)wd * NGATE + j * 4]);
        }

        // stage h(t) hi/lo [32 b x 256 k] bf16, pitch HP
        {
            const uint4* hb = (const uint4*)(g_hsplit + ((size_t)(cur * 2 + dir) * BB + bt * 32) * DH);
#pragma unroll
            for (int it = 0; it < 16; it++) {
                int i = tid + it * 128;
                int b = i >> 6, c4 = i & 63;
                uint4 v = __ldcg(hb + b * 64 + c4);
                u32 hi0 = __byte_perm(v.x, v.y, 0x5410);
                u32 hi1 = __byte_perm(v.z, v.w, 0x5410);
                u32 lo0 = __byte_perm(v.x, v.y, 0x7632);
                u32 lo1 = __byte_perm(v.z, v.w, 0x7632);
                int k0 = c4 * 4;
                *(ull*)(smem + SM_HHI + (b * HP + k0) * 2) = (ull)hi0 | ((ull)hi1 << 32);
                *(ull*)(smem + SM_HLO + (b * HP + k0) * 2) = (ull)lo0 | ((ull)lo1 << 32);
            }
        }
        __syncthreads();

        // fused 2-pass MMA: per warp 32 gate rows x 32 batch, K=256
        float acc[2][4][4];
#pragma unroll
        for (int mt = 0; mt < 2; mt++)
#pragma unroll
            for (int nt = 0; nt < 4; nt++)
#pragma unroll
                for (int q = 0; q < 4; q++) acc[mt][nt][q] = 0.f;

#pragma unroll
        for (int kt = 0; kt < 16; kt++) {
            u32 koff = (u32)(kt * 32);
            u32 af0[4], af1[4], bh[8], bl[8];
            ldsm4(af0, sbase + SM_UHI + aoff0 + koff);
            ldsm4(af1, sbase + SM_UHI + aoff1 + koff);
            ldsm4(bh,     sbase + SM_HHI + boff0 + koff);
            ldsm4(bh + 4, sbase + SM_HHI + boff1 + koff);
            ldsm4(bl,     sbase + SM_HLO + boff0 + koff);
            ldsm4(bl + 4, sbase + SM_HLO + boff1 + koff);
            mma16816(acc[0][0], af0, bh + 0);
            mma16816(acc[0][1], af0, bh + 2);
            mma16816(acc[0][2], af0, bh + 4);
            mma16816(acc[0][3], af0, bh + 6);
            mma16816(acc[1][0], af1, bh + 0);
            mma16816(acc[1][1], af1, bh + 2);
            mma16816(acc[1][2], af1, bh + 4);
            mma16816(acc[1][3], af1, bh + 6);
            mma16816(acc[0][0], af0, bl + 0);
            mma16816(acc[0][1], af0, bl + 2);
            mma16816(acc[0][2], af0, bl + 4);
            mma16816(acc[0][3], af0, bl + 6);
            mma16816(acc[1][0], af1, bl + 0);
            mma16816(acc[1][1], af1, bl + 2);
            mma16816(acc[1][2], af1, bl + 4);
            mma16816(acc[1][3], af1, bl + 6);
        }

        // write gates to smem [row][batch], pitch GP
#pragma unroll
        for (int mt = 0; mt < 2; mt++) {
#pragma unroll
            for (int nt = 0; nt < 4; nt++) {
                int row0 = w * 32 + mt * 16 + (lid >> 2);
                int col = nt * 8 + (lid & 3) * 2;
                *(float2*)&gates_sm[row0 * GP + col] =
                    make_float2(acc[mt][nt][0], acc[mt][nt][1]);
                *(float2*)&gates_sm[(row0 + 8) * GP + col] =
                    make_float2(acc[mt][nt][2], acc[mt][nt][3]);
            }
        }
        __syncthreads();

        // epilogue: per (j, 8 batches) activations + c update
        float hout[8];
#pragma unroll
        for (int r = 0; r < 8; r++) {
            int b = ty * 8 + r;
            float gi = gates_sm[(0 * 32 + tx) * GP + b] + e[r].x;
            float gf = gates_sm[(1 * 32 + tx) * GP + b] + e[r].y;
            float go = gates_sm[(2 * 32 + tx) * GP + b] + e[r].z;
            float gc = gates_sm[(3 * 32 + tx) * GP + b] + e[r].w;
            gi = fsig(gi); gf = fsig(gf); go = fsig(go); gc = ftanh(gc);
            c[r] = gf * c[r] + gi * gc;
            hout[r] = go * ftanh(c[r]);
        }
        u32* hdst = g_hsplit + ((size_t)(nxt * 2 + dir) * BB + bbase) * DH + j;
#pragma unroll
        for (int r = 0; r < 8; r++) {
            u16 hi, lo;
            bsplit(hout[r], hi, lo);
            __stcg(hdst + (size_t)r * DH, (u32)hi | ((u32)lo << 16));
        }
        if (t == SS - 1) {
#pragma unroll
            for (int r = 0; r < 8; r++)
                g_h[(size_t)dir * DH * BB + (size_t)j * BB + bbase + r] = hout[r];
        }

        __syncthreads();
        if (t < SS - 1) {
            if (tid == 0) {
                asm volatile("st.release.gpu.u32 [%0], %1;"
                             :: "l"(&g_flags[grp * 64 + js * 8]), "r"(t + 1) : "memory");
            }
            if (tid < 8) {
                unsigned* fp = &g_flags[grp * 64 + tid * 8];
                unsigned v;
                do {
                    asm volatile("ld.acquire.gpu.u32 %0, [%1];"
                                 : "=r"(v) : "l"(fp) : "memory");
                } while ((int)v < t + 1);
            }
            __syncthreads();
        }
    }
}

// ---------------- kernel 3: output layer ----------------
__global__ void out_kernel(const float* __restrict__ outW,
                           const float* __restrict__ outb,
                           float* __restrict__ pred) {
    int b = blockIdx.x;
    int tid = threadIdx.x;
    const float* hl = g_h;
    const float* hr = g_h + (size_t)DH * BB;
    float a0 = 0.f, a1 = 0.f;
    for (int idx = tid; idx < 512; idx += 128) {
        float v = (idx < 256) ? hl[idx * BB + b] : hr[(idx - 256) * BB + b];
        a0 += v * outW[idx];
        a1 += v * outW[512 + idx];
    }
#pragma unroll
    for (int o = 16; o > 0; o >>= 1) {
        a0 += __shfl_down_sync(0xFFFFFFFFu, a0, o);
        a1 += __shfl_down_sync(0xFFFFFFFFu, a1, o);
    }
    __shared__ float s0[4], s1[4];
    if ((tid & 31) == 0) { s0[tid >> 5] = a0; s1[tid >> 5] = a1; }
    __syncthreads();
    if (tid == 0) {
        pred[b * 2 + 0] = s0[0] + s0[1] + s0[2] + s0[3] + outb[0];
        pred[b * 2 + 1] = s1[0] + s1[1] + s1[2] + s1[3] + outb[1];
    }
}

// ---------------- launch ----------------
extern "C" void kernel_launch(void* const* d_in, const int* in_sizes, int n_in,
                              void* d_out, int out_size) {
    const int*   words = (const int*)d_in[0];
    const float* Emb   = (const float*)d_in[1];
    const float* W     = (const float*)d_in[2];
    const float* U     = (const float*)d_in[3];
    const float* bias  = (const float*)d_in[4];
    const float* outW  = (const float*)d_in[5];
    const float* outb  = (const float*)d_in[6];
    float* pred = (float*)d_out;

    cudaFuncSetAttribute(scan_kernel, cudaFuncAttributeMaxDynamicSharedMemorySize, SM_TOTAL);
    cudaFuncSetAttribute(ew_gemm2, cudaFuncAttributeMaxDynamicSharedMemorySize, EW_SMEM);

    reset_kernel<<<256, 256>>>(words);
    ew_gemm2<<<dim3((NDICT + 127) / 128, NGATE / 128), 256, EW_SMEM>>>(Emb, W, bias);
    scan_kernel<<<NBLK, 128, SM_TOTAL>>>(U);
    out_kernel<<<256, 128>>>(outW, outb, pred);
}

// round 8
// speedup vs baseline: 2.5820x; 1.0323x over previous
#include <cuda_runtime.h>
#include <cuda_bf16.h>
#include <cstdint>

typedef unsigned long long ull;
typedef unsigned int u32;
typedef unsigned short u16;

// ---------------- constants ----------------
#define NDICT   50000
#define DIN     256
#define DH      256
#define NGATE   1024
#define BB      256
#define SS      512
#define NBLK    128

// ---- scan smem (bytes); pitches conflict-free for ldmatrix
#define AP 264                      // U row pitch in bf16 (33 x 16B)
#define HP 264                      // h row pitch in bf16
#define SM_UHI   0
#define SM_HHI   (SM_UHI + 128 * AP * 2)          // 67584
#define SM_HLO   (SM_HHI + 32 * HP * 2)           // 84480
#define SM_TOTAL (SM_HLO + 32 * HP * 2)           // 101376 B

// ---- ew_gemm2 smem (bytes); pitch 72 bf16 = 144 B
#define EP 72
#define EW_AH 0
#define EW_AL (EW_AH + 128 * EP * 2)
#define EW_BH (EW_AL + 128 * EP * 2)
#define EW_BL (EW_BH + 128 * EP * 2)
#define EW_BIAS (EW_BL + 128 * EP * 2)
#define EW_SMEM (EW_BIAS + 128 * 4)

// ---------------- device scratch ----------------
__device__ float g_EW[(size_t)NDICT * NGATE];  // Emb@W^T + bias, cols permuted j*4+type
__device__ u32   g_hsplit[2 * 2 * BB * DH];    // [buf][dir][b][k] packed bf16 hi | lo<<16
__device__ float g_h[2 * DH * BB];             // final h [dir][j][b] fp32
__device__ int   g_wordsT[SS * BB];
__device__ unsigned g_flags[16 * 64];          // [group][js*8]

// ---------------- helpers ----------------
__device__ __forceinline__ u32 smem_u32(const void* p) {
    u32 a; asm("{ .reg .u64 t; cvta.to.shared.u64 t, %1; cvt.u32.u64 %0, t; }"
               : "=r"(a) : "l"(p));
    return a;
}
__device__ __forceinline__ float fsig(float x) {
    float e = __expf(-x);
    return __fdividef(1.0f, 1.0f + e);
}
__device__ __forceinline__ float ftanh(float x) {
    float ax = fabsf(x);
    float e  = __expf(-2.0f * ax);
    float r  = __fdividef(1.0f - e, 1.0f + e);
    return copysignf(r, x);
}
__device__ __forceinline__ void ldsm4(u32* r, u32 addr) {
    asm volatile("ldmatrix.sync.aligned.m8n8.x4.shared.b16 {%0,%1,%2,%3}, [%4];"
                 : "=r"(r[0]), "=r"(r[1]), "=r"(r[2]), "=r"(r[3]) : "r"(addr));
}
__device__ __forceinline__ void mma16816(float* c, const u32* a, const u32* b) {
    asm volatile("mma.sync.aligned.m16n8k16.row.col.f32.bf16.bf16.f32 "
                 "{%0,%1,%2,%3}, {%4,%5,%6,%7}, {%8,%9}, {%0,%1,%2,%3};"
                 : "+f"(c[0]), "+f"(c[1]), "+f"(c[2]), "+f"(c[3])
                 : "r"(a[0]), "r"(a[1]), "r"(a[2]), "r"(a[3]), "r"(b[0]), "r"(b[1]));
}
__device__ __forceinline__ void bsplit(float x, u16& hi, u16& lo) {
    __nv_bfloat16 h = __float2bfloat16(x);
    __nv_bfloat16 l = __float2bfloat16(x - __bfloat162float(h));
    hi = __bfloat16_as_ushort(h);
    lo = __bfloat16_as_ushort(l);
}

// ---------------- kernel 0: reset ----------------
__global__ void reset_kernel(const int* __restrict__ words) {
    int idx = blockIdx.x * blockDim.x + threadIdx.x;
    if (idx < 16 * 64) g_flags[idx] = 0u;
    for (int i = idx; i < 2 * BB * DH; i += gridDim.x * blockDim.x) g_hsplit[i] = 0u;
    for (int i = idx; i < SS * BB; i += gridDim.x * blockDim.x) {
        int s = i >> 8, b = i & 255;
        g_wordsT[i] = words[b * SS + s];
    }
}

// ---------------- kernel 1: EW = Emb @ W^T (+bias), split-bf16 HMMA ----------------
__global__ __launch_bounds__(256) void ew_gemm2(const float* __restrict__ Emb,
                                                const float* __restrict__ W,
                                                const float* __restrict__ bias) {
    extern __shared__ __align__(16) char esm[];
    u32 sb = smem_u32(esm);
    float* biasp = (float*)(esm + EW_BIAS);

    int tid = threadIdx.x;
    int w = tid >> 5, lid = tid & 31;
    int mbase = blockIdx.x * 128;
    int nbase = blockIdx.y * 128;
    int wm = (w & 3) * 32, wn = (w >> 2) * 64;

    if (tid < 128) {
        int colp = nbase + tid;
        biasp[tid] = bias[(colp & 3) * 256 + (colp >> 2)];
    }

    int idx4 = lid >> 3, r8 = lid & 7;
    u32 aoff0 = (u32)(((wm + (idx4 & 1) * 8 + r8) * EP + (idx4 >> 1) * 8) * 2);
    u32 aoff1 = aoff0 + (u32)(16 * EP * 2);
    u32 boffB = (u32)(((wn + (idx4 >> 1) * 8 + r8) * EP + (idx4 & 1) * 8) * 2);

    float acc[2][8][4];
#pragma unroll
    for (int mt = 0; mt < 2; mt++)
#pragma unroll
        for (int n8 = 0; n8 < 8; n8++)
#pragma unroll
            for (int q = 0; q < 4; q++) acc[mt][n8][q] = 0.f;

    for (int kb = 0; kb < 4; kb++) {
        int k0 = kb * 64;
        for (int i = tid; i < 128 * 16; i += 256) {
            int row = i >> 4, kq = (i & 15) * 4;
            int va = mbase + row;
            float4 v = make_float4(0.f, 0.f, 0.f, 0.f);
            if (va < NDICT) v = *(const float4*)&Emb[(size_t)va * DIN + k0 + kq];
            u16 h0, l0, h1, l1, h2, l2, h3, l3;
            bsplit(v.x, h0, l0); bsplit(v.y, h1, l1);
            bsplit(v.z, h2, l2); bsplit(v.w, h3, l3);
            u32* ah = (u32*)(esm + EW_AH + (row * EP + kq) * 2);
            u32* al = (u32*)(esm + EW_AL + (row * EP + kq) * 2);
            ah[0] = (u32)h0 | ((u32)h1 << 16); ah[1] = (u32)h2 | ((u32)h3 << 16);
            al[0] = (u32)l0 | ((u32)l1 << 16); al[1] = (u32)l2 | ((u32)l3 << 16);
        }
        for (int i = tid; i < 128 * 16; i += 256) {
            int row = i >> 4, kq = (i & 15) * 4;
            int colp = nbase + row;
            int grow = (colp & 3) * 256 + (colp >> 2);
            float4 v = *(const float4*)&W[(size_t)grow * DIN + k0 + kq];
            u16 h0, l0, h1, l1, h2, l2, h3, l3;
            bsplit(v.x, h0, l0); bsplit(v.y, h1, l1);
            bsplit(v.z, h2, l2); bsplit(v.w, h3, l3);
            u32* bh = (u32*)(esm + EW_BH + (row * EP + kq) * 2);
            u32* bl = (u32*)(esm + EW_BL + (row * EP + kq) * 2);
            bh[0] = (u32)h0 | ((u32)h1 << 16); bh[1] = (u32)h2 | ((u32)h3 << 16);
            bl[0] = (u32)l0 | ((u32)l1 << 16); bl[1] = (u32)l2 | ((u32)l3 << 16);
        }
        __syncthreads();

#pragma unroll
        for (int kt = 0; kt < 4; kt++) {
            u32 koff = (u32)(kt * 32);
            u32 a0h[4], a1h[4], a0l[4], a1l[4];
            ldsm4(a0h, sb + EW_AH + aoff0 + koff);
            ldsm4(a1h, sb + EW_AH + aoff1 + koff);
            ldsm4(a0l, sb + EW_AL + aoff0 + koff);
            ldsm4(a1l, sb + EW_AL + aoff1 + koff);
#pragma unroll
            for (int p = 0; p < 4; p++) {
                u32 po = (u32)(p * 16 * EP * 2);
                u32 bh[4], bl[4];
                ldsm4(bh, sb + EW_BH + boffB + po + koff);
                ldsm4(bl, sb + EW_BL + boffB + po + koff);
                mma16816(acc[0][2 * p + 0], a0h, bh + 0);
                mma16816(acc[0][2 * p + 1], a0h, bh + 2);
                mma16816(acc[1][2 * p + 0], a1h, bh + 0);
                mma16816(acc[1][2 * p + 1], a1h, bh + 2);
                mma16816(acc[0][2 * p + 0], a0h, bl + 0);
                mma16816(acc[0][2 * p + 1], a0h, bl + 2);
                mma16816(acc[1][2 * p + 0], a1h, bl + 0);
                mma16816(acc[1][2 * p + 1], a1h, bl + 2);
                mma16816(acc[0][2 * p + 0], a0l, bh + 0);
                mma16816(acc[0][2 * p + 1], a0l, bh + 2);
                mma16816(acc[1][2 * p + 0], a1l, bh + 0);
                mma16816(acc[1][2 * p + 1], a1l, bh + 2);
            }
        }
        __syncthreads();
    }

#pragma unroll
    for (int mt = 0; mt < 2; mt++) {
#pragma unroll
        for (int n8 = 0; n8 < 8; n8++) {
            int nl = wn + n8 * 8 + (lid & 3) * 2;
            int col = nbase + nl;
            float b0 = biasp[nl], b1 = biasp[nl + 1];
            int r0 = mbase + wm + mt * 16 + (lid >> 2);
            if (r0 < NDICT)
                *(float2*)&g_EW[(size_t)r0 * NGATE + col] =
                    make_float2(acc[mt][n8][0] + b0, acc[mt][n8][1] + b1);
            if (r0 + 8 < NDICT)
                *(float2*)&g_EW[(size_t)(r0 + 8) * NGATE + col] =
                    make_float2(acc[mt][n8][2] + b0, acc[mt][n8][3] + b1);
        }
    }
}

// ---------------- kernel 2: persistent scan — register-epilogue HMMA ----------------
// grid = 128 CTAs: dir(2) x batch-tile(8, 32 rows) x gate-slice(8, 32 j)
// Warp-tile rows r = w*32 + type*8 + jl  -> each thread owns all 4 gates of one j
__global__ __launch_bounds__(128, 1) void scan_kernel(const float* __restrict__ U) {
    extern __shared__ __align__(16) char smem[];
    u32 sbase = smem_u32(smem);

    int tid = threadIdx.x;
    int w = tid >> 5, lid = tid & 31;
    int bx = blockIdx.x;
    int dir = bx >> 6;
    int bt  = (bx >> 3) & 7;
    int js  = bx & 7;
    int grp = bx >> 3;

    int j = js * 32 + w * 8 + (lid >> 2);   // this thread's hidden unit
    // this thread's 8 batch columns: b[r] = (r>>1)*8 + (lid&3)*2 + (r&1)
    int bcol[8];
#pragma unroll
    for (int r = 0; r < 8; r++) bcol[r] = (r >> 1) * 8 + (lid & 3) * 2 + (r & 1);

    // preload U slice (bf16 hi), rows r = w2*32 + type*8 + jl
    for (int i = tid; i < 128 * 256; i += 128) {
        int r = i >> 8, k = i & 255;
        int w2 = r >> 5, type = (r >> 3) & 3, jl = r & 7;
        float u = U[(size_t)(type * 256 + js * 32 + w2 * 8 + jl) * DH + k];
        *(__nv_bfloat16*)(smem + SM_UHI + (r * AP + k) * 2) = __float2bfloat16(u);
    }

    int idx4 = lid >> 3, r8 = lid & 7;
    u32 aoff0 = (u32)(((w * 32 + (idx4 & 1) * 8 + r8) * AP + (idx4 >> 1) * 8) * 2);
    u32 aoff1 = aoff0 + (u32)(16 * AP * 2);
    u32 boff0 = (u32)((((idx4 >> 1) * 8 + r8) * HP + (idx4 & 1) * 8) * 2);
    u32 boff1 = boff0 + (u32)(16 * HP * 2);

    float c[8];
#pragma unroll
    for (int r = 0; r < 8; r++) c[r] = 0.f;
    __syncthreads();

    for (int t = 0; t < SS; t++) {
        int cur = t & 1, nxt = cur ^ 1;
        int s = dir ? (SS - 1 - t) : t;

        // EW prefetch: e[r] = [i,f,o,c] inputs for (j, bcol[r])
        float4 e[8];
#pragma unroll
        for (int r = 0; r < 8; r++) {
            int wd = g_wordsT[s * BB + bt * 32 + bcol[r]];
            e[r] = __ldg((const float4*)&g_EW[(size_t)wd * NGATE + j * 4]);
        }

        // stage h(t) hi/lo [32 b x 256 k] bf16, pitch HP
        {
            const uint4* hb = (const uint4*)(g_hsplit + ((size_t)(cur * 2 + dir) * BB + bt * 32) * DH);
#pragma unroll
            for (int it = 0; it < 16; it++) {
                int i = tid + it * 128;
                int b = i >> 6, c4 = i & 63;
                uint4 v = __ldcg(hb + b * 64 + c4);
                u32 hi0 = __byte_perm(v.x, v.y, 0x5410);
                u32 hi1 = __byte_perm(v.z, v.w, 0x5410);
                u32 lo0 = __byte_perm(v.x, v.y, 0x7632);
                u32 lo1 = __byte_perm(v.z, v.w, 0x7632);
                int k0 = c4 * 4;
                *(ull*)(smem + SM_HHI + (b * HP + k0) * 2) = (ull)hi0 | ((ull)hi1 << 32);
                *(ull*)(smem + SM_HLO + (b * HP + k0) * 2) = (ull)lo0 | ((ull)lo1 << 32);
            }
        }
        __syncthreads();

        // fused 2-pass MMA: warp computes rows w*32..w*32+31 (8 j x 4 types), 32 batch
        float acc[2][4][4];
#pragma unroll
        for (int mt = 0; mt < 2; mt++)
#pragma unroll
            for (int nt = 0; nt < 4; nt++)
#pragma unroll
                for (int q = 0; q < 4; q++) acc[mt][nt][q] = 0.f;

#pragma unroll
        for (int kt = 0; kt < 16; kt++) {
            u32 koff = (u32)(kt * 32);
            u32 af0[4], af1[4], bh[8], bl[8];
            ldsm4(af0, sbase + SM_UHI + aoff0 + koff);
            ldsm4(af1, sbase + SM_UHI + aoff1 + koff);
            ldsm4(bh,     sbase + SM_HHI + boff0 + koff);
            ldsm4(bh + 4, sbase + SM_HHI + boff1 + koff);
            ldsm4(bl,     sbase + SM_HLO + boff0 + koff);
            ldsm4(bl + 4, sbase + SM_HLO + boff1 + koff);
            mma16816(acc[0][0], af0, bh + 0);
            mma16816(acc[0][1], af0, bh + 2);
            mma16816(acc[0][2], af0, bh + 4);
            mma16816(acc[0][3], af0, bh + 6);
            mma16816(acc[1][0], af1, bh + 0);
            mma16816(acc[1][1], af1, bh + 2);
            mma16816(acc[1][2], af1, bh + 4);
            mma16816(acc[1][3], af1, bh + 6);
            mma16816(acc[0][0], af0, bl + 0);
            mma16816(acc[0][1], af0, bl + 2);
            mma16816(acc[0][2], af0, bl + 4);
            mma16816(acc[0][3], af0, bl + 6);
            mma16816(acc[1][0], af1, bl + 0);
            mma16816(acc[1][1], af1, bl + 2);
            mma16816(acc[1][2], af1, bl + 4);
            mma16816(acc[1][3], af1, bl + 6);
        }

        // register epilogue: rows lid/4 + {0,8,16,24} = types {i,f,o,c} of unit j
        //   gi = acc[0][nt][c], gf = acc[0][nt][2+c], go = acc[1][nt][c], gc = acc[1][nt][2+c]
        float hout[8];
#pragma unroll
        for (int r = 0; r < 8; r++) {
            int nt = r >> 1, q = r & 1;
            float gi = fsig (acc[0][nt][q]     + e[r].x);
            float gf = fsig (acc[0][nt][2 + q] + e[r].y);
            float go = fsig (acc[1][nt][q]     + e[r].z);
            float gc = ftanh(acc[1][nt][2 + q] + e[r].w);
            c[r] = gf * c[r] + gi * gc;
            hout[r] = go * ftanh(c[r]);
        }

        // pack h -> bf16 hi|lo u32, store to global [b][k=j]
        u32* hbuf = g_hsplit + (size_t)(nxt * 2 + dir) * BB * DH + (size_t)bt * 32 * DH + j;
#pragma unroll
        for (int r = 0; r < 8; r++) {
            u16 hi, lo;
            bsplit(hout[r], hi, lo);
            __stcg(hbuf + (size_t)bcol[r] * DH, (u32)hi | ((u32)lo << 16));
        }
        if (t == SS - 1) {
#pragma unroll
            for (int r = 0; r < 8; r++)
                g_h[(size_t)dir * DH * BB + (size_t)j * BB + bt * 32 + bcol[r]] = hout[r];
        }

        __syncthreads();   // hs reads done before next overwrite; h stores issued
        if (t < SS - 1) {
            if (tid == 0) {
                asm volatile("st.release.gpu.u32 [%0], %1;"
                             :: "l"(&g_flags[grp * 64 + js * 8]), "r"(t + 1) : "memory");
            }
            if (tid < 8) {
                unsigned* fp = &g_flags[grp * 64 + tid * 8];
                unsigned v;
                do {
                    asm volatile("ld.acquire.gpu.u32 %0, [%1];"
                                 : "=r"(v) : "l"(fp) : "memory");
                } while ((int)v < t + 1);
            }
            __syncthreads();
        }
    }
}

// ---------------- kernel 3: output layer ----------------
__global__ void out_kernel(const float* __restrict__ outW,
                           const float* __restrict__ outb,
                           float* __restrict__ pred) {
    int b = blockIdx.x;
    int tid = threadIdx.x;
    const float* hl = g_h;
    const float* hr = g_h + (size_t)DH * BB;
    float a0 = 0.f, a1 = 0.f;
    for (int idx = tid; idx < 512; idx += 128) {
        float v = (idx < 256) ? hl[idx * BB + b] : hr[(idx - 256) * BB + b];
        a0 += v * outW[idx];
        a1 += v * outW[512 + idx];
    }
#pragma unroll
    for (int o = 16; o > 0; o >>= 1) {
        a0 += __shfl_down_sync(0xFFFFFFFFu, a0, o);
        a1 += __shfl_down_sync(0xFFFFFFFFu, a1, o);
    }
    __shared__ float s0[4], s1[4];
    if ((tid & 31) == 0) { s0[tid >> 5] = a0; s1[tid >> 5] = a1; }
    __syncthreads();
    if (tid == 0) {
        pred[b * 2 + 0] = s0[0] + s0[1] + s0[2] + s0[3] + outb[0];
        pred[b * 2 + 1] = s1[0] + s1[1] + s1[2] + s1[3] + outb[1];
    }
}

// ---------------- launch ----------------
extern "C" void kernel_launch(void* const* d_in, const int* in_sizes, int n_in,
                              void* d_out, int out_size) {
    const int*   words = (const int*)d_in[0];
    const float* Emb   = (const float*)d_in[1];
    const float* W     = (const float*)d_in[2];
    const float* U     = (const float*)d_in[3];
    const float* bias  = (const float*)d_in[4];
    const float* outW  = (const float*)d_in[5];
    const float* outb  = (const float*)d_in[6];
    float* pred = (float*)d_out;

    cudaFuncSetAttribute(scan_kernel, cudaFuncAttributeMaxDynamicSharedMemorySize, SM_TOTAL);
    cudaFuncSetAttribute(ew_gemm2, cudaFuncAttributeMaxDynamicSharedMemorySize, EW_SMEM);

    reset_kernel<<<256, 256>>>(words);
    ew_gemm2<<<dim3((NDICT + 127) / 128, NGATE / 128), 256, EW_SMEM>>>(Emb, W, bias);
    scan_kernel<<<NBLK, 128, SM_TOTAL>>>(U);
    out_kernel<<<256, 128>>>(outW, outb, pred);
}